// round 9
// baseline (speedup 1.0000x reference)
#include <cuda_runtime.h>

// DistMult edge scoring, R9: R8 (4 edges/warp, 8 lanes/edge) restructured
// for 32 registers -> full occupancy.
//   out[e] = sigmoid( sum_d h[src[e]][d] * W[rel[e]][d] * h[dst[e]][d] )
// h: [100000,128] f32 (L2-resident), W: [6,128] f32 (L1-resident), idx int32.
//
// R8 post-mortem: 13.4 wf-cyc/edge at L1=76.8%, but occ reg-capped at 73.5%
// (40 regs). This version does the dot product in 4 phases of one float4
// position each (3 live float4 = 12 regs) and pins 32 regs via
// __launch_bounds__(128, 16) -> 2048 threads/SM. SM-wide MLP comes from
// 64 warps x 3 outstanding loads, not per-thread ILP.

#define WPB 4
#define TPB (WPB * 32)
#define GRID_BLOCKS (148 * 16)

__global__ __launch_bounds__(TPB, 16)
void distmult_kernel(const float* __restrict__ h,
                     const float* __restrict__ W,
                     const int* __restrict__ src,
                     const int* __restrict__ dst,
                     const int* __restrict__ rel,
                     float* __restrict__ out,
                     int E)
{
    const int lane = threadIdx.x & 31;
    const int sub  = lane & 7;    // lane within 8-lane edge group
    const int grp  = lane >> 3;   // which of 4 edges in the warp

    const float4* __restrict__ h4 = reinterpret_cast<const float4*>(h);
    const float4* __restrict__ W4 = reinterpret_cast<const float4*>(W);

    const int warp_glb  = blockIdx.x * WPB + (threadIdx.x >> 5);
    const int warp_step = gridDim.x * WPB;
    const int nquads    = (E + 3) >> 2;

    for (int q = warp_glb; q < nquads; q += warp_step) {
        int e  = 4 * q + grp;
        int ec = e < E ? e : E - 1;            // tail clamp (dup compute ok)

        int s = __ldg(src + ec);
        int d = __ldg(dst + ec);
        int r = __ldg(rel + ec);

        const float4* __restrict__ up = h4 + s * 32 + sub;
        const float4* __restrict__ vp = h4 + d * 32 + sub;
        const float4* __restrict__ wp = W4 + r * 32 + sub;

        float sum = 0.0f;

        // 4 phases, one float4 position (sub + 8j) per phase.
        // 3 live float4 per phase keeps the kernel at 32 registers.
        #pragma unroll
        for (int j = 0; j < 4; j++) {
            float4 u = __ldg(up + 8 * j);
            float4 v = __ldg(vp + 8 * j);
            float4 w = __ldg(wp + 8 * j);
            sum += u.x * w.x * v.x
                 + u.y * w.y * v.y
                 + u.z * w.z * v.z
                 + u.w * w.w * v.w;
        }

        // 8-lane reduction (xor 4,2,1 stays within each group)
        #pragma unroll
        for (int off = 4; off > 0; off >>= 1)
            sum += __shfl_xor_sync(0xffffffffu, sum, off);

        if (sub == 0 && e < E)
            out[e] = 1.0f / (1.0f + __expf(-sum));
    }
}

extern "C" void kernel_launch(void* const* d_in, const int* in_sizes, int n_in,
                              void* d_out, int out_size)
{
    const float* h   = (const float*)d_in[0];
    const float* W   = (const float*)d_in[1];
    const int*   src = (const int*)d_in[2];
    const int*   dst = (const int*)d_in[3];
    const int*   rel = (const int*)d_in[4];
    float* out = (float*)d_out;

    int E = in_sizes[2];
    if (E <= 0) return;

    int nquads = (E + 3) >> 2;
    int blocks_needed = (nquads + WPB - 1) / WPB;
    if (blocks_needed < 1) blocks_needed = 1;
    int blocks = blocks_needed < GRID_BLOCKS ? blocks_needed : GRID_BLOCKS;
    distmult_kernel<<<blocks, TPB>>>(h, W, src, dst, rel, out, E);
}

// round 10
// speedup vs baseline: 1.0920x; 1.0920x over previous
#include <cuda_runtime.h>

// DistMult edge scoring, R10: R8 body (proven 13.4 wf-cyc/edge) with regs
// squeezed 40 -> 36 via __launch_bounds__(128, 14) => 56 warps/SM (87.5% occ).
//   out[e] = sigmoid( sum_d h[src[e]][d] * W[rel[e]][d] * h[dst[e]][d] )
// h: [100000,128] f32 (L2-resident), W: [6,128] f32 (L1-resident), idx int32.
//
// 4 edges/warp, 8 lanes/edge. Two phases of 6 batched float4 loads each
// (R9 showed 4x3-load phases ADD L1 wavefronts; keep the 6-load batches).
// Every LDG.128 covers 4 rows x 128B = fully coalesced.

#define WPB 4
#define TPB (WPB * 32)
#define GRID_BLOCKS (148 * 14)

__global__ __launch_bounds__(TPB, 14)
void distmult_kernel(const float* __restrict__ h,
                     const float* __restrict__ W,
                     const int* __restrict__ src,
                     const int* __restrict__ dst,
                     const int* __restrict__ rel,
                     float* __restrict__ out,
                     int E)
{
    const int lane = threadIdx.x & 31;
    const int sub  = lane & 7;    // lane within 8-lane edge group
    const int grp  = lane >> 3;   // which of 4 edges

    const float4* __restrict__ h4 = reinterpret_cast<const float4*>(h);
    const float4* __restrict__ W4 = reinterpret_cast<const float4*>(W);

    const int warp_glb  = blockIdx.x * WPB + (threadIdx.x >> 5);
    const int warp_step = gridDim.x * WPB;
    const int nquads    = (E + 3) >> 2;

    for (int q = warp_glb; q < nquads; q += warp_step) {
        int e  = 4 * q + grp;
        int ec = e < E ? e : E - 1;            // tail clamp (dup compute ok)

        int s = __ldg(src + ec);
        int d = __ldg(dst + ec);
        int r = __ldg(rel + ec);

        const float4* __restrict__ up = h4 + s * 32 + sub;
        const float4* __restrict__ vp = h4 + d * 32 + sub;
        const float4* __restrict__ wp = W4 + r * 32 + sub;

        // Phase 1: float4 positions sub, sub+8  (6 loads batched)
        float4 u0 = __ldg(up);
        float4 u1 = __ldg(up + 8);
        float4 v0 = __ldg(vp);
        float4 v1 = __ldg(vp + 8);
        float4 w0 = __ldg(wp);
        float4 w1 = __ldg(wp + 8);

        float sum = u0.x * w0.x * v0.x
                  + u0.y * w0.y * v0.y
                  + u0.z * w0.z * v0.z
                  + u0.w * w0.w * v0.w
                  + u1.x * w1.x * v1.x
                  + u1.y * w1.y * v1.y
                  + u1.z * w1.z * v1.z
                  + u1.w * w1.w * v1.w;

        // Phase 2: float4 positions sub+16, sub+24
        u0 = __ldg(up + 16);
        u1 = __ldg(up + 24);
        v0 = __ldg(vp + 16);
        v1 = __ldg(vp + 24);
        w0 = __ldg(wp + 16);
        w1 = __ldg(wp + 24);

        sum += u0.x * w0.x * v0.x
             + u0.y * w0.y * v0.y
             + u0.z * w0.z * v0.z
             + u0.w * w0.w * v0.w
             + u1.x * w1.x * v1.x
             + u1.y * w1.y * v1.y
             + u1.z * w1.z * v1.z
             + u1.w * w1.w * v1.w;

        // 8-lane reduction (xor 4,2,1 stays within each group)
        #pragma unroll
        for (int off = 4; off > 0; off >>= 1)
            sum += __shfl_xor_sync(0xffffffffu, sum, off);

        if (sub == 0 && e < E)
            out[e] = 1.0f / (1.0f + __expf(-sum));
    }
}

extern "C" void kernel_launch(void* const* d_in, const int* in_sizes, int n_in,
                              void* d_out, int out_size)
{
    const float* h   = (const float*)d_in[0];
    const float* W   = (const float*)d_in[1];
    const int*   src = (const int*)d_in[2];
    const int*   dst = (const int*)d_in[3];
    const int*   rel = (const int*)d_in[4];
    float* out = (float*)d_out;

    int E = in_sizes[2];
    if (E <= 0) return;

    int nquads = (E + 3) >> 2;
    int blocks_needed = (nquads + WPB - 1) / WPB;
    if (blocks_needed < 1) blocks_needed = 1;
    int blocks = blocks_needed < GRID_BLOCKS ? blocks_needed : GRID_BLOCKS;
    distmult_kernel<<<blocks, TPB>>>(h, W, src, dst, rel, out, E);
}

// round 11
// speedup vs baseline: 1.1213x; 1.0269x over previous
#include <cuda_runtime.h>

// DistMult edge scoring, R11: R8/R10 body (13.4 wf-cyc/edge, 32 regs)
// relaunched with 256-thread blocks.
//   out[e] = sigmoid( sum_d h[src[e]][d] * W[rel[e]][d] * h[dst[e]][d] )
// h: [100000,128] f32 (L2-resident), W: [6,128] f32 (L1-resident), idx int32.
//
// Evidence: R6 (TPB=256) hit L1=89.3% util; all TPB=128 variants cap at
// ~78% regardless of occupancy (R8 occ 73% vs R10 occ 85%: same dur).
// Hypothesis: 8-warp blocks give each SMSP a deeper, better-mixed eligible
// pool -> higher achieved L1tex issue rate. Body unchanged:
// 4 edges/warp, 8 lanes/edge, two phases of 6 batched float4 LDG.128s.

#define WPB 8
#define TPB (WPB * 32)
#define GRID_BLOCKS (148 * 8)

__global__ __launch_bounds__(TPB, 8)
void distmult_kernel(const float* __restrict__ h,
                     const float* __restrict__ W,
                     const int* __restrict__ src,
                     const int* __restrict__ dst,
                     const int* __restrict__ rel,
                     float* __restrict__ out,
                     int E)
{
    const int lane = threadIdx.x & 31;
    const int sub  = lane & 7;    // lane within 8-lane edge group
    const int grp  = lane >> 3;   // which of 4 edges

    const float4* __restrict__ h4 = reinterpret_cast<const float4*>(h);
    const float4* __restrict__ W4 = reinterpret_cast<const float4*>(W);

    const int warp_glb  = blockIdx.x * WPB + (threadIdx.x >> 5);
    const int warp_step = gridDim.x * WPB;
    const int nquads    = (E + 3) >> 2;

    for (int q = warp_glb; q < nquads; q += warp_step) {
        int e  = 4 * q + grp;
        int ec = e < E ? e : E - 1;            // tail clamp (dup compute ok)

        int s = __ldg(src + ec);
        int d = __ldg(dst + ec);
        int r = __ldg(rel + ec);

        const float4* __restrict__ up = h4 + s * 32 + sub;
        const float4* __restrict__ vp = h4 + d * 32 + sub;
        const float4* __restrict__ wp = W4 + r * 32 + sub;

        // Phase 1: float4 positions sub, sub+8  (6 loads batched)
        float4 u0 = __ldg(up);
        float4 u1 = __ldg(up + 8);
        float4 v0 = __ldg(vp);
        float4 v1 = __ldg(vp + 8);
        float4 w0 = __ldg(wp);
        float4 w1 = __ldg(wp + 8);

        float sum = u0.x * w0.x * v0.x
                  + u0.y * w0.y * v0.y
                  + u0.z * w0.z * v0.z
                  + u0.w * w0.w * v0.w
                  + u1.x * w1.x * v1.x
                  + u1.y * w1.y * v1.y
                  + u1.z * w1.z * v1.z
                  + u1.w * w1.w * v1.w;

        // Phase 2: float4 positions sub+16, sub+24
        u0 = __ldg(up + 16);
        u1 = __ldg(up + 24);
        v0 = __ldg(vp + 16);
        v1 = __ldg(vp + 24);
        w0 = __ldg(wp + 16);
        w1 = __ldg(wp + 24);

        sum += u0.x * w0.x * v0.x
             + u0.y * w0.y * v0.y
             + u0.z * w0.z * v0.z
             + u0.w * w0.w * v0.w
             + u1.x * w1.x * v1.x
             + u1.y * w1.y * v1.y
             + u1.z * w1.z * v1.z
             + u1.w * w1.w * v1.w;

        // 8-lane reduction (xor 4,2,1 stays within each group)
        #pragma unroll
        for (int off = 4; off > 0; off >>= 1)
            sum += __shfl_xor_sync(0xffffffffu, sum, off);

        if (sub == 0 && e < E)
            out[e] = 1.0f / (1.0f + __expf(-sum));
    }
}

extern "C" void kernel_launch(void* const* d_in, const int* in_sizes, int n_in,
                              void* d_out, int out_size)
{
    const float* h   = (const float*)d_in[0];
    const float* W   = (const float*)d_in[1];
    const int*   src = (const int*)d_in[2];
    const int*   dst = (const int*)d_in[3];
    const int*   rel = (const int*)d_in[4];
    float* out = (float*)d_out;

    int E = in_sizes[2];
    if (E <= 0) return;

    int nquads = (E + 3) >> 2;
    int blocks_needed = (nquads + WPB - 1) / WPB;
    if (blocks_needed < 1) blocks_needed = 1;
    int blocks = blocks_needed < GRID_BLOCKS ? blocks_needed : GRID_BLOCKS;
    distmult_kernel<<<blocks, TPB>>>(h, W, src, dst, rel, out, E);
}